// round 8
// baseline (speedup 1.0000x reference)
#include <cuda_runtime.h>
#include <cuda_fp16.h>
#include <math.h>
#include <stdint.h>

#define IN_DIM   2048
#define OUT_DIM  2048
#define RNK      4
#define LUTN     16
#define NORM_EPS 1e-6f
#define MAG_EPS  1e-6f

// GEMM config: single-pass fp16, K = 2048, BK = 64
#define NSTEP   32               // 2048 / 64
#define STAGES  3
#define ROWB    144              // 64 fp16 = 128B data + 16B pad (9 coprime 8 -> conflict-free ldsm)
#define ATILE_BYTES (128 * ROWB) // 18432
#define STAGE_BYTES (2 * ATILE_BYTES)
#define SMEM_TOTAL  (STAGES * STAGE_BYTES)   // 110592 -> 2 CTAs/SM

// ---------------- device scratch ----------------
__device__ float d_nA[RNK];
__device__ float d_nB[RNK];
__device__ float d_g[RNK];
__device__ __align__(1024) __half d_Ah[(size_t)8192 * IN_DIM];     // x as fp16 [M, 2048]
__device__ __align__(1024) __half d_Bh[(size_t)OUT_DIM * IN_DIM];  // W as fp16 [N, 2048]

// ---------------- PTX helpers ----------------
__device__ __forceinline__ uint32_t smem_u32(const void* p) {
    uint32_t a;
    asm("{ .reg .u64 t; cvta.to.shared.u64 t, %1; cvt.u32.u64 %0, t; }" : "=r"(a) : "l"(p));
    return a;
}
#define CP_ASYNC16(s, g) \
    asm volatile("cp.async.cg.shared.global [%0], [%1], 16;" :: "r"(s), "l"(g) : "memory")
#define CP_COMMIT() asm volatile("cp.async.commit_group;" ::: "memory")
#define CP_WAIT(N)  asm volatile("cp.async.wait_group %0;" :: "n"(N) : "memory")

__device__ __forceinline__ void ldm_x4(uint32_t& r0, uint32_t& r1, uint32_t& r2, uint32_t& r3,
                                       uint32_t addr) {
    asm volatile("ldmatrix.sync.aligned.m8n8.x4.shared.b16 {%0,%1,%2,%3}, [%4];"
                 : "=r"(r0), "=r"(r1), "=r"(r2), "=r"(r3) : "r"(addr));
}
__device__ __forceinline__ void mma_f16(float& c0, float& c1, float& c2, float& c3,
                                        uint32_t a0, uint32_t a1, uint32_t a2, uint32_t a3,
                                        uint32_t b0, uint32_t b1) {
    asm volatile(
        "mma.sync.aligned.m16n8k16.row.col.f32.f16.f16.f32 "
        "{%0,%1,%2,%3}, {%4,%5,%6,%7}, {%8,%9}, {%0,%1,%2,%3};"
        : "+f"(c0), "+f"(c1), "+f"(c2), "+f"(c3)
        : "r"(a0), "r"(a1), "r"(a2), "r"(a3), "r"(b0), "r"(b1));
}

// ---------------- kernel 1: rank norms + softplus magnitudes ----------------
__global__ void prep_norms_kernel(const float* __restrict__ sA,
                                  const float* __restrict__ sB,
                                  const float* __restrict__ mag) {
    int w = threadIdx.x >> 5, lane = threadIdx.x & 31;
    int r = w & 3;
    float s = 0.f;
    if (w < 4) {
        for (int o = lane; o < OUT_DIM; o += 32) { float v = sA[o * RNK + r]; s += v * v; }
    } else {
        for (int i = lane; i < IN_DIM; i += 32) { float v = sB[r * IN_DIM + i]; s += v * v; }
    }
    #pragma unroll
    for (int off = 16; off; off >>= 1) s += __shfl_xor_sync(0xffffffffu, s, off);
    if (lane == 0) {
        float n = fmaxf(sqrtf(s), NORM_EPS);
        if (w < 4) d_nA[r] = n; else d_nB[r] = n;
    }
    if (threadIdx.x < RNK) {
        float m = mag[threadIdx.x];
        float sp = (m > 20.f) ? m : log1pf(expf(m));
        d_g[threadIdx.x] = sp + MAG_EPS;
    }
}

// ---------------- kernel 2: x -> fp16 ----------------
__global__ void convert_x_kernel(const float* __restrict__ x) {
    size_t t = (size_t)blockIdx.x * blockDim.x + threadIdx.x;
    size_t base = t * 4;
    float4 v = *(const float4*)(x + base);
    __half2 h0 = __floats2half2_rn(v.x, v.y);
    __half2 h1 = __floats2half2_rn(v.z, v.w);
    *(uint2*)&d_Ah[base] = make_uint2(*(uint32_t*)&h0, *(uint32_t*)&h1);
}

// ---------------- kernel 3: build W -> fp16 ----------------
__global__ void build_w_kernel(const int* __restrict__ idx,
                               const float* __restrict__ lut,
                               const float* __restrict__ sA,
                               const float* __restrict__ sB) {
    __shared__ float lutS[LUTN];
    if (threadIdx.x < LUTN) lutS[threadIdx.x] = lut[threadIdx.x];
    __syncthreads();

    size_t t = (size_t)blockIdx.x * blockDim.x + threadIdx.x;
    size_t base = t * 4;
    int o = (int)(base >> 11);
    int i0 = (int)(base & 2047);

    float cA[RNK];
    #pragma unroll
    for (int r = 0; r < RNK; r++)
        cA[r] = fabsf(sA[o * RNK + r]) * d_g[r] / (d_nA[r] * d_nB[r]);

    int4 id4 = *(const int4*)(idx + (size_t)o * IN_DIM + i0);
    int ids[4] = {id4.x, id4.y, id4.z, id4.w};
    float w[4];
    #pragma unroll
    for (int j = 0; j < 4; j++) {
        int i = i0 + j;
        float s = 0.f;
        #pragma unroll
        for (int r = 0; r < RNK; r++)
            s += cA[r] * fabsf(sB[r * IN_DIM + i]);
        w[j] = lutS[ids[j]] * s;
    }
    __half2 h0 = __floats2half2_rn(w[0], w[1]);
    __half2 h1 = __floats2half2_rn(w[2], w[3]);
    *(uint2*)&d_Bh[base] = make_uint2(*(uint32_t*)&h0, *(uint32_t*)&h1);
}

// ---------------- kernel 4: fp16 GEMM, CTA 128x128, 8 warps of 64x32, BK=64 ----------------
__global__ __launch_bounds__(256, 2)
void gemm_kernel(const float* __restrict__ bias, float* __restrict__ y) {
    extern __shared__ char smem[];
    const uint32_t sbase = smem_u32(smem);

    const int tid = threadIdx.x, lane = tid & 31, wid = tid >> 5;
    const int warp_m = wid & 1, warp_n = wid >> 1;     // 2 x 4 warps, 64x32 warp tiles
    const int m0 = blockIdx.y * 128, n0 = blockIdx.x * 128;

    // loader mapping: 2 threads/row, 4 x 16B chunks each (BK=64 -> 128B/row)
    const int lr = tid >> 1, lc = tid & 1;
    const __half* Ag = d_Ah + (size_t)m0 * IN_DIM;
    const __half* Bg = d_Bh + (size_t)n0 * IN_DIM;

    const uint32_t aLaneOff = (uint32_t)(lane & 15) * ROWB + (uint32_t)(lane >> 4) * 16;
    const uint32_t bLaneOff = (uint32_t)((lane & 7) + ((lane >> 4) << 3)) * ROWB
                            + (uint32_t)((lane >> 3) & 1) * 16;

    float acc[4][4][4];
    #pragma unroll
    for (int i = 0; i < 4; i++)
        #pragma unroll
        for (int j = 0; j < 4; j++)
            #pragma unroll
            for (int q = 0; q < 4; q++) acc[i][j][q] = 0.f;

    auto issue = [&](int t) {
        int slot = t % STAGES;
        int kk = t << 6;
        uint32_t sA = sbase + slot * STAGE_BYTES;
        uint32_t sB = sA + ATILE_BYTES;
        const __half* ga = Ag + (size_t)lr * IN_DIM + kk + lc * 32;
        const __half* gb = Bg + (size_t)lr * IN_DIM + kk + lc * 32;
        uint32_t la = sA + lr * ROWB + lc * 64;
        uint32_t lb = sB + lr * ROWB + lc * 64;
        #pragma unroll
        for (int c = 0; c < 4; c++) {
            CP_ASYNC16(la + c * 16, (const char*)(ga + c * 8));
            CP_ASYNC16(lb + c * 16, (const char*)(gb + c * 8));
        }
        CP_COMMIT();
    };

    // prologue: 2 stages in flight
    issue(0); issue(1);

    for (int t = 0; t < NSTEP; t++) {
        if (t + 1 < NSTEP) { CP_WAIT(1); } else { CP_WAIT(0); }
        __syncthreads();   // stage t visible; slot (t+2)%3 (= slot t-1) free for refill

        if (t + 2 < NSTEP) issue(t + 2);

        uint32_t sA = sbase + (t % STAGES) * STAGE_BYTES
                    + (uint32_t)(warp_m * 64) * ROWB + aLaneOff;
        uint32_t sB = sbase + (t % STAGES) * STAGE_BYTES + ATILE_BYTES
                    + (uint32_t)(warp_n * 32) * ROWB + bLaneOff;
        #pragma unroll
        for (int k16 = 0; k16 < 4; k16++) {
            uint32_t a[4][4], b[2][4];
            #pragma unroll
            for (int mi = 0; mi < 4; mi++)
                ldm_x4(a[mi][0], a[mi][1], a[mi][2], a[mi][3],
                       sA + (uint32_t)(mi * 16) * ROWB + k16 * 32);
            #pragma unroll
            for (int p = 0; p < 2; p++)
                ldm_x4(b[p][0], b[p][1], b[p][2], b[p][3],
                       sB + (uint32_t)(p * 16) * ROWB + k16 * 32);
            #pragma unroll
            for (int mi = 0; mi < 4; mi++)
                #pragma unroll
                for (int ni = 0; ni < 4; ni++) {
                    uint32_t b0 = b[ni >> 1][(ni & 1) * 2];
                    uint32_t b1 = b[ni >> 1][(ni & 1) * 2 + 1];
                    mma_f16(acc[mi][ni][0], acc[mi][ni][1], acc[mi][ni][2], acc[mi][ni][3],
                            a[mi][0], a[mi][1], a[mi][2], a[mi][3], b0, b1);
                }
        }
        // no trailing barrier: next iteration's barrier orders slot reuse
    }

    // ---- epilogue: + bias, float2 stores ----
    #pragma unroll
    for (int ni = 0; ni < 4; ni++) {
        int col = n0 + warp_n * 32 + ni * 8 + (lane & 3) * 2;
        float2 bb = *(const float2*)(bias + col);
        #pragma unroll
        for (int mi = 0; mi < 4; mi++) {
            int r0 = m0 + warp_m * 64 + mi * 16 + (lane >> 2);
            float2 v0, v1;
            v0.x = acc[mi][ni][0] + bb.x; v0.y = acc[mi][ni][1] + bb.y;
            v1.x = acc[mi][ni][2] + bb.x; v1.y = acc[mi][ni][3] + bb.y;
            *(float2*)(y + (size_t)r0 * OUT_DIM + col)       = v0;
            *(float2*)(y + (size_t)(r0 + 8) * OUT_DIM + col) = v1;
        }
    }
}

// ---------------- host ----------------
extern "C" void kernel_launch(void* const* d_in, const int* in_sizes, int n_in,
                              void* d_out, int out_size) {
    const float* x       = (const float*)d_in[0];
    const int*   indices = (const int*)d_in[1];
    const float* lut     = (const float*)d_in[2];
    const float* sA      = (const float*)d_in[3];
    const float* sB      = (const float*)d_in[4];
    const float* mag     = (const float*)d_in[5];
    const float* bias    = (const float*)d_in[6];
    float*       y       = (float*)d_out;

    int M = in_sizes[0] / IN_DIM;   // 8192

    cudaFuncSetAttribute(gemm_kernel, cudaFuncAttributeMaxDynamicSharedMemorySize, SMEM_TOTAL);

    prep_norms_kernel<<<1, 256>>>(sA, sB, mag);
    convert_x_kernel<<<(int)((size_t)M * IN_DIM / 4 / 256), 256>>>(x);
    build_w_kernel<<<(OUT_DIM * IN_DIM / 4) / 256, 256>>>(indices, lut, sA, sB);
    gemm_kernel<<<dim3(OUT_DIM / 128, M / 128), 256, SMEM_TOTAL>>>(bias, y);
}

// round 9
// speedup vs baseline: 1.2195x; 1.2195x over previous
#include <cuda_runtime.h>
#include <cuda_fp16.h>
#include <math.h>
#include <stdint.h>

#define IN_DIM   2048
#define OUT_DIM  2048
#define RNK      4
#define LUTN     16
#define NORM_EPS 1e-6f
#define MAG_EPS  1e-6f

// GEMM config: single-pass fp16, K = 2048 (R5-proven shape)
#define NSTEP   64               // 2048 / 32
#define STAGES  4
#define ROWB    80               // 32 fp16 = 64B data + 16B pad (5 coprime 8 -> conflict-free ldsm)
#define ATILE_BYTES (128 * ROWB) // 10240
#define STAGE_BYTES (2 * ATILE_BYTES)
#define SMEM_TOTAL  (STAGES * STAGE_BYTES)   // 81920 -> 2 CTAs/SM

// ---------------- device scratch ----------------
__device__ float d_nA[RNK];
__device__ float d_nB[RNK];
__device__ float d_g[RNK];
__device__ __align__(1024) __half d_Ah[(size_t)8192 * IN_DIM];     // x as fp16 [M, 2048]
__device__ __align__(1024) __half d_Bh[(size_t)OUT_DIM * IN_DIM];  // W as fp16 [N, 2048]

// ---------------- PTX helpers ----------------
__device__ __forceinline__ uint32_t smem_u32(const void* p) {
    uint32_t a;
    asm("{ .reg .u64 t; cvta.to.shared.u64 t, %1; cvt.u32.u64 %0, t; }" : "=r"(a) : "l"(p));
    return a;
}
#define CP_ASYNC16(s, g) \
    asm volatile("cp.async.cg.shared.global [%0], [%1], 16;" :: "r"(s), "l"(g) : "memory")
#define CP_COMMIT() asm volatile("cp.async.commit_group;" ::: "memory")
#define CP_WAIT(N)  asm volatile("cp.async.wait_group %0;" :: "n"(N) : "memory")

__device__ __forceinline__ void ldm_x4(uint32_t& r0, uint32_t& r1, uint32_t& r2, uint32_t& r3,
                                       uint32_t addr) {
    asm volatile("ldmatrix.sync.aligned.m8n8.x4.shared.b16 {%0,%1,%2,%3}, [%4];"
                 : "=r"(r0), "=r"(r1), "=r"(r2), "=r"(r3) : "r"(addr));
}
__device__ __forceinline__ void mma_f16(float& c0, float& c1, float& c2, float& c3,
                                        uint32_t a0, uint32_t a1, uint32_t a2, uint32_t a3,
                                        uint32_t b0, uint32_t b1) {
    asm volatile(
        "mma.sync.aligned.m16n8k16.row.col.f32.f16.f16.f32 "
        "{%0,%1,%2,%3}, {%4,%5,%6,%7}, {%8,%9}, {%0,%1,%2,%3};"
        : "+f"(c0), "+f"(c1), "+f"(c2), "+f"(c3)
        : "r"(a0), "r"(a1), "r"(a2), "r"(a3), "r"(b0), "r"(b1));
}

// ---------------- kernel 1: rank norms + softplus magnitudes (8 blocks) ----------------
__global__ void prep_norms_kernel(const float* __restrict__ sA,
                                  const float* __restrict__ sB,
                                  const float* __restrict__ mag) {
    __shared__ float red[8];
    int b = blockIdx.x;            // 0..3: nA[b], 4..7: nB[b-4]
    int tid = threadIdx.x, lane = tid & 31, w = tid >> 5;
    float s = 0.f;
    if (b < 4) {
        for (int o = tid; o < OUT_DIM; o += 256) { float v = sA[o * RNK + b]; s += v * v; }
    } else {
        int r = b - 4;
        for (int i = tid; i < IN_DIM; i += 256) { float v = sB[r * IN_DIM + i]; s += v * v; }
    }
    #pragma unroll
    for (int off = 16; off; off >>= 1) s += __shfl_xor_sync(0xffffffffu, s, off);
    if (lane == 0) red[w] = s;
    __syncthreads();
    if (tid == 0) {
        float t = 0.f;
        #pragma unroll
        for (int i = 0; i < 8; i++) t += red[i];
        float n = fmaxf(sqrtf(t), NORM_EPS);
        if (b < 4) d_nA[b] = n; else d_nB[b - 4] = n;
        if (b == 0) {
            #pragma unroll
            for (int r = 0; r < RNK; r++) {
                float m = mag[r];
                float sp = (m > 20.f) ? m : log1pf(expf(m));
                d_g[r] = sp + MAG_EPS;
            }
        }
    }
}

// ---------------- kernel 2: fused convert (x -> fp16) + build W (-> fp16) ----------------
// blocks [0, XBLK): convert x ; blocks [XBLK, XBLK+WBLK): build W
__global__ void convert_kernel(const float* __restrict__ x,
                               const int* __restrict__ idx,
                               const float* __restrict__ lut,
                               const float* __restrict__ sA,
                               const float* __restrict__ sB,
                               int xblk) {
    if (blockIdx.x < (unsigned)xblk) {
        size_t t = (size_t)blockIdx.x * blockDim.x + threadIdx.x;
        size_t base = t * 4;
        float4 v = *(const float4*)(x + base);
        __half2 h0 = __floats2half2_rn(v.x, v.y);
        __half2 h1 = __floats2half2_rn(v.z, v.w);
        *(uint2*)&d_Ah[base] = make_uint2(*(uint32_t*)&h0, *(uint32_t*)&h1);
        return;
    }
    __shared__ float lutS[LUTN];
    if (threadIdx.x < LUTN) lutS[threadIdx.x] = lut[threadIdx.x];
    __syncthreads();

    size_t t = (size_t)(blockIdx.x - xblk) * blockDim.x + threadIdx.x;
    size_t base = t * 4;
    int o = (int)(base >> 11);
    int i0 = (int)(base & 2047);

    float cA[RNK];
    #pragma unroll
    for (int r = 0; r < RNK; r++)
        cA[r] = fabsf(sA[o * RNK + r]) * d_g[r] / (d_nA[r] * d_nB[r]);

    int4 id4 = *(const int4*)(idx + (size_t)o * IN_DIM + i0);
    int ids[4] = {id4.x, id4.y, id4.z, id4.w};
    float w[4];
    #pragma unroll
    for (int j = 0; j < 4; j++) {
        int i = i0 + j;
        float s = 0.f;
        #pragma unroll
        for (int r = 0; r < RNK; r++)
            s += cA[r] * fabsf(sB[r * IN_DIM + i]);
        w[j] = lutS[ids[j]] * s;
    }
    __half2 h0 = __floats2half2_rn(w[0], w[1]);
    __half2 h1 = __floats2half2_rn(w[2], w[3]);
    *(uint2*)&d_Bh[base] = make_uint2(*(uint32_t*)&h0, *(uint32_t*)&h1);
}

// ---------------- kernel 3: fp16 GEMM, CTA 128x128, 8 warps of 64x32, 2 CTAs/SM ----------------
__global__ __launch_bounds__(256, 2)
void gemm_kernel(const float* __restrict__ bias, float* __restrict__ y) {
    extern __shared__ char smem[];
    const uint32_t sbase = smem_u32(smem);

    const int tid = threadIdx.x, lane = tid & 31, wid = tid >> 5;
    const int warp_m = wid & 1, warp_n = wid >> 1;     // 2 x 4 warps, 64x32 warp tiles
    const int m0 = blockIdx.y * 128, n0 = blockIdx.x * 128;

    // loader: 4 threads/row, 16B each -> 64B contiguous per row (R5-proven)
    const int lr = tid >> 2, lc = tid & 3;
    const __half* Ag = d_Ah + (size_t)m0 * IN_DIM;
    const __half* Bg = d_Bh + (size_t)n0 * IN_DIM;

    const uint32_t aLaneOff = (uint32_t)(lane & 15) * ROWB + (uint32_t)(lane >> 4) * 16;
    const uint32_t bLaneOff = (uint32_t)((lane & 7) + ((lane >> 4) << 3)) * ROWB
                            + (uint32_t)((lane >> 3) & 1) * 16;

    float acc[4][4][4];
    #pragma unroll
    for (int i = 0; i < 4; i++)
        #pragma unroll
        for (int j = 0; j < 4; j++)
            #pragma unroll
            for (int q = 0; q < 4; q++) acc[i][j][q] = 0.f;

    auto issue = [&](int t) {
        int slot = t & (STAGES - 1);
        int kk = t << 5;
        uint32_t sA = sbase + slot * STAGE_BYTES;
        uint32_t sB = sA + ATILE_BYTES;
        CP_ASYNC16(sA + lr * ROWB + lc * 16,
                   (const char*)(Ag + (size_t)lr * IN_DIM + kk + lc * 8));
        CP_ASYNC16(sA + (lr + 64) * ROWB + lc * 16,
                   (const char*)(Ag + (size_t)(lr + 64) * IN_DIM + kk + lc * 8));
        CP_ASYNC16(sB + lr * ROWB + lc * 16,
                   (const char*)(Bg + (size_t)lr * IN_DIM + kk + lc * 8));
        CP_ASYNC16(sB + (lr + 64) * ROWB + lc * 16,
                   (const char*)(Bg + (size_t)(lr + 64) * IN_DIM + kk + lc * 8));
        CP_COMMIT();
    };

    // prologue: 3 stages in flight
    #pragma unroll
    for (int s = 0; s < STAGES - 1; s++) issue(s);

    for (int t = 0; t < NSTEP; t++) {
        if (t + STAGES - 1 < NSTEP) { CP_WAIT(2); } else { CP_WAIT(0); }
        __syncthreads();   // stage t visible; also orders last iter's reads before slot reuse

        if (t + STAGES - 1 < NSTEP) issue(t + STAGES - 1);

        uint32_t sA = sbase + (t & (STAGES - 1)) * STAGE_BYTES
                    + (uint32_t)(warp_m * 64) * ROWB + aLaneOff;
        uint32_t sB = sbase + (t & (STAGES - 1)) * STAGE_BYTES + ATILE_BYTES
                    + (uint32_t)(warp_n * 32) * ROWB + bLaneOff;
        #pragma unroll
        for (int k16 = 0; k16 < 2; k16++) {
            uint32_t a[4][4], b[2][4];
            #pragma unroll
            for (int mi = 0; mi < 4; mi++)
                ldm_x4(a[mi][0], a[mi][1], a[mi][2], a[mi][3],
                       sA + (uint32_t)(mi * 16) * ROWB + k16 * 32);
            #pragma unroll
            for (int p = 0; p < 2; p++)
                ldm_x4(b[p][0], b[p][1], b[p][2], b[p][3],
                       sB + (uint32_t)(p * 16) * ROWB + k16 * 32);
            #pragma unroll
            for (int mi = 0; mi < 4; mi++)
                #pragma unroll
                for (int ni = 0; ni < 4; ni++) {
                    uint32_t b0 = b[ni >> 1][(ni & 1) * 2];
                    uint32_t b1 = b[ni >> 1][(ni & 1) * 2 + 1];
                    mma_f16(acc[mi][ni][0], acc[mi][ni][1], acc[mi][ni][2], acc[mi][ni][3],
                            a[mi][0], a[mi][1], a[mi][2], a[mi][3], b0, b1);
                }
        }
        // no trailing barrier: next iteration's top barrier orders slot reuse
    }

    // ---- epilogue: + bias, float2 stores ----
    #pragma unroll
    for (int ni = 0; ni < 4; ni++) {
        int col = n0 + warp_n * 32 + ni * 8 + (lane & 3) * 2;
        float2 bb = *(const float2*)(bias + col);
        #pragma unroll
        for (int mi = 0; mi < 4; mi++) {
            int r0 = m0 + warp_m * 64 + mi * 16 + (lane >> 2);
            float2 v0, v1;
            v0.x = acc[mi][ni][0] + bb.x; v0.y = acc[mi][ni][1] + bb.y;
            v1.x = acc[mi][ni][2] + bb.x; v1.y = acc[mi][ni][3] + bb.y;
            *(float2*)(y + (size_t)r0 * OUT_DIM + col)       = v0;
            *(float2*)(y + (size_t)(r0 + 8) * OUT_DIM + col) = v1;
        }
    }
}

// ---------------- host ----------------
extern "C" void kernel_launch(void* const* d_in, const int* in_sizes, int n_in,
                              void* d_out, int out_size) {
    const float* x       = (const float*)d_in[0];
    const int*   indices = (const int*)d_in[1];
    const float* lut     = (const float*)d_in[2];
    const float* sA      = (const float*)d_in[3];
    const float* sB      = (const float*)d_in[4];
    const float* mag     = (const float*)d_in[5];
    const float* bias    = (const float*)d_in[6];
    float*       y       = (float*)d_out;

    int M = in_sizes[0] / IN_DIM;   // 8192
    int xblk = (int)((size_t)M * IN_DIM / 4 / 256);          // 8192
    int wblk = (OUT_DIM * IN_DIM / 4) / 256;                 // 2048

    cudaFuncSetAttribute(gemm_kernel, cudaFuncAttributeMaxDynamicSharedMemorySize, SMEM_TOTAL);

    prep_norms_kernel<<<8, 256>>>(sA, sB, mag);
    convert_kernel<<<xblk + wblk, 256>>>(x, indices, lut, sA, sB, xblk);
    gemm_kernel<<<dim3(OUT_DIM / 128, M / 128), 256, SMEM_TOTAL>>>(bias, y);
}

// round 10
// speedup vs baseline: 1.5638x; 1.2823x over previous
#include <cuda_runtime.h>
#include <cuda_fp16.h>
#include <math.h>
#include <stdint.h>

#define IN_DIM   2048
#define OUT_DIM  2048
#define RNK      4
#define LUTN     16
#define NORM_EPS 1e-6f
#define MAG_EPS  1e-6f

// GEMM config: single-pass fp16, K = 2048, mbarrier ring
#define NSTEP   64               // 2048 / 32
#define STAGES  5
#define DEPTH   3                // fill-ahead; slack = STAGES-DEPTH = 2 iters of warp slide
#define ROWB    80               // 32 fp16 = 64B data + 16B pad (5 coprime 8 -> conflict-free ldsm)
#define ATILE_BYTES (128 * ROWB) // 10240
#define STAGE_BYTES (2 * ATILE_BYTES)
#define SMEM_TOTAL  (128 + STAGES * STAGE_BYTES)   // 102528 -> 2 CTAs/SM

// ---------------- device scratch ----------------
__device__ float d_nA[RNK];
__device__ float d_nB[RNK];
__device__ float d_g[RNK];
__device__ __align__(1024) __half d_Ah[(size_t)8192 * IN_DIM];     // x as fp16 [M, 2048]
__device__ __align__(1024) __half d_Bh[(size_t)OUT_DIM * IN_DIM];  // W as fp16 [N, 2048]

// ---------------- PTX helpers (plain sm_103-safe: sm_80/sm_90 features) ----------------
__device__ __forceinline__ uint32_t smem_u32(const void* p) {
    uint32_t a;
    asm("{ .reg .u64 t; cvta.to.shared.u64 t, %1; cvt.u32.u64 %0, t; }" : "=r"(a) : "l"(p));
    return a;
}
#define CP_ASYNC16(s, g) \
    asm volatile("cp.async.cg.shared.global [%0], [%1], 16;" :: "r"(s), "l"(g) : "memory")
#define MBAR_INIT(a, c) \
    asm volatile("mbarrier.init.shared.b64 [%0], %1;" :: "r"(a), "r"(c) : "memory")
#define MBAR_ARRIVE(a) \
    asm volatile("mbarrier.arrive.shared.b64 _, [%0];" :: "r"(a) : "memory")
#define CP_MBAR_ARRIVE(a) \
    asm volatile("cp.async.mbarrier.arrive.noinc.shared.b64 [%0];" :: "r"(a) : "memory")

__device__ __forceinline__ void mbar_wait(uint32_t mbar, uint32_t parity) {
    asm volatile(
        "{\n\t.reg .pred P;\n\t"
        "W%=:\n\t"
        "mbarrier.try_wait.parity.acquire.cta.shared::cta.b64 P, [%0], %1, 0x989680;\n\t"
        "@P bra.uni D%=;\n\t"
        "bra.uni W%=;\n\t"
        "D%=:\n\t}"
        :: "r"(mbar), "r"(parity) : "memory");
}

__device__ __forceinline__ void ldm_x4(uint32_t& r0, uint32_t& r1, uint32_t& r2, uint32_t& r3,
                                       uint32_t addr) {
    asm volatile("ldmatrix.sync.aligned.m8n8.x4.shared.b16 {%0,%1,%2,%3}, [%4];"
                 : "=r"(r0), "=r"(r1), "=r"(r2), "=r"(r3) : "r"(addr));
}
__device__ __forceinline__ void mma_f16(float& c0, float& c1, float& c2, float& c3,
                                        uint32_t a0, uint32_t a1, uint32_t a2, uint32_t a3,
                                        uint32_t b0, uint32_t b1) {
    asm volatile(
        "mma.sync.aligned.m16n8k16.row.col.f32.f16.f16.f32 "
        "{%0,%1,%2,%3}, {%4,%5,%6,%7}, {%8,%9}, {%0,%1,%2,%3};"
        : "+f"(c0), "+f"(c1), "+f"(c2), "+f"(c3)
        : "r"(a0), "r"(a1), "r"(a2), "r"(a3), "r"(b0), "r"(b1));
}

// ---------------- kernel 1: rank norms + softplus magnitudes (8 blocks) ----------------
__global__ void prep_norms_kernel(const float* __restrict__ sA,
                                  const float* __restrict__ sB,
                                  const float* __restrict__ mag) {
    __shared__ float red[8];
    int b = blockIdx.x;            // 0..3: nA[b], 4..7: nB[b-4]
    int tid = threadIdx.x, lane = tid & 31, w = tid >> 5;
    float s = 0.f;
    if (b < 4) {
        for (int o = tid; o < OUT_DIM; o += 256) { float v = sA[o * RNK + b]; s += v * v; }
    } else {
        int r = b - 4;
        for (int i = tid; i < IN_DIM; i += 256) { float v = sB[r * IN_DIM + i]; s += v * v; }
    }
    #pragma unroll
    for (int off = 16; off; off >>= 1) s += __shfl_xor_sync(0xffffffffu, s, off);
    if (lane == 0) red[w] = s;
    __syncthreads();
    if (tid == 0) {
        float t = 0.f;
        #pragma unroll
        for (int i = 0; i < 8; i++) t += red[i];
        float n = fmaxf(sqrtf(t), NORM_EPS);
        if (b < 4) d_nA[b] = n; else d_nB[b - 4] = n;
        if (b == 0) {
            #pragma unroll
            for (int r = 0; r < RNK; r++) {
                float m = mag[r];
                float sp = (m > 20.f) ? m : log1pf(expf(m));
                d_g[r] = sp + MAG_EPS;
            }
        }
    }
}

// ---------------- kernel 2: fused convert (x -> fp16) + build W (-> fp16) ----------------
__global__ void convert_kernel(const float* __restrict__ x,
                               const int* __restrict__ idx,
                               const float* __restrict__ lut,
                               const float* __restrict__ sA,
                               const float* __restrict__ sB,
                               int xblk) {
    if (blockIdx.x < (unsigned)xblk) {
        size_t t = (size_t)blockIdx.x * blockDim.x + threadIdx.x;
        size_t base = t * 4;
        float4 v = *(const float4*)(x + base);
        __half2 h0 = __floats2half2_rn(v.x, v.y);
        __half2 h1 = __floats2half2_rn(v.z, v.w);
        *(uint2*)&d_Ah[base] = make_uint2(*(uint32_t*)&h0, *(uint32_t*)&h1);
        return;
    }
    __shared__ float lutS[LUTN];
    if (threadIdx.x < LUTN) lutS[threadIdx.x] = lut[threadIdx.x];
    __syncthreads();

    size_t t = (size_t)(blockIdx.x - xblk) * blockDim.x + threadIdx.x;
    size_t base = t * 4;
    int o = (int)(base >> 11);
    int i0 = (int)(base & 2047);

    float cA[RNK];
    #pragma unroll
    for (int r = 0; r < RNK; r++)
        cA[r] = fabsf(sA[o * RNK + r]) * d_g[r] / (d_nA[r] * d_nB[r]);

    int4 id4 = *(const int4*)(idx + (size_t)o * IN_DIM + i0);
    int ids[4] = {id4.x, id4.y, id4.z, id4.w};
    float w[4];
    #pragma unroll
    for (int j = 0; j < 4; j++) {
        int i = i0 + j;
        float s = 0.f;
        #pragma unroll
        for (int r = 0; r < RNK; r++)
            s += cA[r] * fabsf(sB[r * IN_DIM + i]);
        w[j] = lutS[ids[j]] * s;
    }
    __half2 h0 = __floats2half2_rn(w[0], w[1]);
    __half2 h1 = __floats2half2_rn(w[2], w[3]);
    *(uint2*)&d_Bh[base] = make_uint2(*(uint32_t*)&h0, *(uint32_t*)&h1);
}

// ---------------- kernel 3: fp16 GEMM, mbarrier ring, CTA 128x128, 2 CTAs/SM ----------------
__global__ __launch_bounds__(256, 2)
void gemm_kernel(const float* __restrict__ bias, float* __restrict__ y) {
    extern __shared__ char smem[];
    const uint32_t sbase = smem_u32(smem);
    const uint32_t mbF = sbase;           // full[5]
    const uint32_t mbE = sbase + 64;      // empty[5]
    const uint32_t dbase = sbase + 128;

    const int tid = threadIdx.x, lane = tid & 31, wid = tid >> 5;
    const int warp_m = wid & 1, warp_n = wid >> 1;     // 2 x 4 warps, 64x32 warp tiles
    const int m0 = blockIdx.y * 128, n0 = blockIdx.x * 128;

    const int lr = tid >> 2, lc = tid & 3;
    const __half* Ag = d_Ah + (size_t)m0 * IN_DIM;
    const __half* Bg = d_Bh + (size_t)n0 * IN_DIM;

    const uint32_t aLaneOff = (uint32_t)(lane & 15) * ROWB + (uint32_t)(lane >> 4) * 16;
    const uint32_t bLaneOff = (uint32_t)((lane & 7) + ((lane >> 4) << 3)) * ROWB
                            + (uint32_t)((lane >> 3) & 1) * 16;

    if (tid == 0) {
        #pragma unroll
        for (int s = 0; s < STAGES; s++) {
            MBAR_INIT(mbF + s * 8, 256);   // every thread's cp.async arrive (noinc)
            MBAR_INIT(mbE + s * 8, 8);     // one arrive per warp
        }
    }
    __syncthreads();

    float acc[4][4][4];
    #pragma unroll
    for (int i = 0; i < 4; i++)
        #pragma unroll
        for (int j = 0; j < 4; j++)
            #pragma unroll
            for (int q = 0; q < 4; q++) acc[i][j][q] = 0.f;

    auto issue_cp = [&](int t, int slot) {
        int kk = t << 5;
        uint32_t sA = dbase + slot * STAGE_BYTES;
        uint32_t sB = sA + ATILE_BYTES;
        CP_ASYNC16(sA + lr * ROWB + lc * 16,
                   (const char*)(Ag + (size_t)lr * IN_DIM + kk + lc * 8));
        CP_ASYNC16(sA + (lr + 64) * ROWB + lc * 16,
                   (const char*)(Ag + (size_t)(lr + 64) * IN_DIM + kk + lc * 8));
        CP_ASYNC16(sB + lr * ROWB + lc * 16,
                   (const char*)(Bg + (size_t)lr * IN_DIM + kk + lc * 8));
        CP_ASYNC16(sB + (lr + 64) * ROWB + lc * 16,
                   (const char*)(Bg + (size_t)(lr + 64) * IN_DIM + kk + lc * 8));
        CP_MBAR_ARRIVE(mbF + slot * 8);
    };

    // prologue: fill chunks 0..DEPTH-1 into slots 0..DEPTH-1
    #pragma unroll
    for (int f = 0; f < DEPTH; f++) issue_cp(f, f);

    int cs = 0, cpar = 0;      // consumer slot/parity
    int ps = DEPTH, ppar = 0;  // producer slot/parity of (tf/STAGES)

    for (int t = 0; t < NSTEP; t++) {
        int tf = t + DEPTH;
        if (tf < NSTEP) {
            if (tf >= STAGES) mbar_wait(mbE + ps * 8, ppar ^ 1);  // slot free?
            issue_cp(tf, ps);
            if (++ps == STAGES) { ps = 0; ppar ^= 1; }
        }

        mbar_wait(mbF + cs * 8, cpar);   // chunk t data ready (acquire)

        uint32_t sA = dbase + cs * STAGE_BYTES + (uint32_t)(warp_m * 64) * ROWB + aLaneOff;
        uint32_t sB = dbase + cs * STAGE_BYTES + ATILE_BYTES
                    + (uint32_t)(warp_n * 32) * ROWB + bLaneOff;
        #pragma unroll
        for (int k16 = 0; k16 < 2; k16++) {
            uint32_t a[4][4], b[2][4];
            #pragma unroll
            for (int mi = 0; mi < 4; mi++)
                ldm_x4(a[mi][0], a[mi][1], a[mi][2], a[mi][3],
                       sA + (uint32_t)(mi * 16) * ROWB + k16 * 32);
            #pragma unroll
            for (int p = 0; p < 2; p++)
                ldm_x4(b[p][0], b[p][1], b[p][2], b[p][3],
                       sB + (uint32_t)(p * 16) * ROWB + k16 * 32);
            #pragma unroll
            for (int mi = 0; mi < 4; mi++)
                #pragma unroll
                for (int ni = 0; ni < 4; ni++) {
                    uint32_t b0 = b[ni >> 1][(ni & 1) * 2];
                    uint32_t b1 = b[ni >> 1][(ni & 1) * 2 + 1];
                    mma_f16(acc[mi][ni][0], acc[mi][ni][1], acc[mi][ni][2], acc[mi][ni][3],
                            a[mi][0], a[mi][1], a[mi][2], a[mi][3], b0, b1);
                }
        }

        __syncwarp();
        if (lane == 0) MBAR_ARRIVE(mbE + cs * 8);   // this warp done with slot cs
        if (++cs == STAGES) { cs = 0; cpar ^= 1; }
    }

    // ---- epilogue: + bias, float2 stores (per-warp independent) ----
    #pragma unroll
    for (int ni = 0; ni < 4; ni++) {
        int col = n0 + warp_n * 32 + ni * 8 + (lane & 3) * 2;
        float2 bb = *(const float2*)(bias + col);
        #pragma unroll
        for (int mi = 0; mi < 4; mi++) {
            int r0 = m0 + warp_m * 64 + mi * 16 + (lane >> 2);
            float2 v0, v1;
            v0.x = acc[mi][ni][0] + bb.x; v0.y = acc[mi][ni][1] + bb.y;
            v1.x = acc[mi][ni][2] + bb.x; v1.y = acc[mi][ni][3] + bb.y;
            *(float2*)(y + (size_t)r0 * OUT_DIM + col)       = v0;
            *(float2*)(y + (size_t)(r0 + 8) * OUT_DIM + col) = v1;
        }
    }
}

// ---------------- host ----------------
extern "C" void kernel_launch(void* const* d_in, const int* in_sizes, int n_in,
                              void* d_out, int out_size) {
    const float* x       = (const float*)d_in[0];
    const int*   indices = (const int*)d_in[1];
    const float* lut     = (const float*)d_in[2];
    const float* sA      = (const float*)d_in[3];
    const float* sB      = (const float*)d_in[4];
    const float* mag     = (const float*)d_in[5];
    const float* bias    = (const float*)d_in[6];
    float*       y       = (float*)d_out;

    int M = in_sizes[0] / IN_DIM;   // 8192
    int xblk = (int)((size_t)M * IN_DIM / 4 / 256);          // 8192
    int wblk = (OUT_DIM * IN_DIM / 4) / 256;                 // 2048

    cudaFuncSetAttribute(gemm_kernel, cudaFuncAttributeMaxDynamicSharedMemorySize, SMEM_TOTAL);

    prep_norms_kernel<<<8, 256>>>(sA, sB, mag);
    convert_kernel<<<xblk + wblk, 256>>>(x, indices, lut, sA, sB, xblk);
    gemm_kernel<<<dim3(OUT_DIM / 128, M / 128), 256, SMEM_TOTAL>>>(bias, y);
}